// round 14
// baseline (speedup 1.0000x reference)
#include <cuda_runtime.h>
#include <cuda_bf16.h>
#include <cstdint>

#define B_TOT   32768
#define SAMP    16
#define D       256
#define NREL    238
#define BM      64
#define NTHREADS 256

// ---------------- device-global scratch ----------------
__device__ __align__(16) uint32_t g_Bfh[32768];   // W bf16x2 hi, mma B-fragment order
__device__ __align__(16) uint32_t g_Bfl[32768];   // W bf16x2 residual
__device__ __align__(16) float g_rwT[NREL * D];   // relation_weight transposed [r][d]

// ---------------- smem layout for k_main (bytes) ----------------
#define SM_IDX    0             // 1024 ints = 4096
#define SM_STAGE  4096          // 2 stages x 16384 (one row: 16 samples x 1KB)
#define SM_AH     36864         // 64 * 528
#define SM_AL     70656         // 64 * 528  -> end 104448
#define SM_REL    4096          // overlays STAGE/AH after GEMM: 64 x 1056
#define SM_TOTAL  104448
#define A_PITCH   528
#define REL_PITCH_B 1056

// ---------------- helpers ----------------
__device__ __forceinline__ uint32_t smem_u32(const void* p) {
    uint32_t a;
    asm("{ .reg .u64 t; cvta.to.shared.u64 t, %1; cvt.u32.u64 %0, t; }" : "=r"(a) : "l"(p));
    return a;
}
__device__ __forceinline__ void cp_async16(uint32_t dst, const void* src) {
    asm volatile("cp.async.cg.shared.global [%0], [%1], 16;" :: "r"(dst), "l"(src));
}
#define CP_COMMIT() asm volatile("cp.async.commit_group;" ::: "memory")
#define CP_WAIT(n)  asm volatile("cp.async.wait_group %0;" :: "n"(n) : "memory")
__device__ __forceinline__ void ldsm4(uint32_t& r0, uint32_t& r1, uint32_t& r2,
                                      uint32_t& r3, uint32_t addr) {
    asm volatile("ldmatrix.sync.aligned.m8n8.x4.shared.b16 {%0,%1,%2,%3}, [%4];"
                 : "=r"(r0), "=r"(r1), "=r"(r2), "=r"(r3) : "r"(addr));
}
__device__ __forceinline__ void mma_bf16(float* c, const uint32_t* a, const uint32_t* b) {
    asm volatile("mma.sync.aligned.m16n8k16.row.col.f32.bf16.bf16.f32 "
                 "{%0,%1,%2,%3}, {%4,%5,%6,%7}, {%8,%9}, {%0,%1,%2,%3};"
                 : "+f"(c[0]), "+f"(c[1]), "+f"(c[2]), "+f"(c[3])
                 : "r"(a[0]), "r"(a[1]), "r"(a[2]), "r"(a[3]), "r"(b[0]), "r"(b[1]));
}

// ---------------- kernel 0: transpose rw + pack W fragments (proven) ----------------
__global__ void k_prep0(const float* __restrict__ rw, const float* __restrict__ W) {
    const int tid = threadIdx.x;
    const int bx  = blockIdx.x;

    g_rwT[bx * D + tid] = rw[tid * NREL + bx];

    if (bx < 64) {
        const int g = bx * 256 + tid;
        const int l = g & 31;
        const int j = (g >> 5) & 31;
        const int i = g >> 10;
        const int n  = j * 8 + (l >> 2);
        const int k0 = i * 16 + (l & 3) * 2;
        #pragma unroll
        for (int r = 0; r < 2; ++r) {
            const int k = k0 + r * 8;
            const float w0 = W[n * 256 + k];
            const float w1 = W[n * 256 + k + 1];
            __nv_bfloat162 h = __floats2bfloat162_rn(w0, w1);
            float2 f = __bfloat1622float2(h);
            __nv_bfloat162 lo = __floats2bfloat162_rn(w0 - f.x, w1 - f.y);
            g_Bfh[2 * g + r] = *(uint32_t*)&h;
            g_Bfl[2 * g + r] = *(uint32_t*)&lo;
        }
    }
}

// ---------------- kernel 1: cp.async gather -> GEMM -> rel -> epilogue ----------------
__global__ __launch_bounds__(NTHREADS, 2) void k_main(const int* __restrict__ nbr,
                                                      const int* __restrict__ rel,
                                                      const float* __restrict__ feat,
                                                      float* __restrict__ out) {
    extern __shared__ char smem[];
    const uint32_t sbase = smem_u32(smem);
    const int tid  = threadIdx.x;
    const int b0   = blockIdx.x * BM;
    const int lane = tid & 31;
    const int warp = tid >> 5;

    ((int4*)(smem + SM_IDX))[tid] = ((const int4*)(nbr + b0 * SAMP))[tid];
    __syncthreads();
    const int* sIdx = (const int*)(smem + SM_IDX);

    // ---------- Phase A: 2-stage cp.async pipeline, one output row per chunk ----------
    // issue(r): stage the 16 sampled feature rows for output row r (16KB)
    // 256 threads x 4 x 16B pieces; piece p: sample=p>>6, seg=p&63
    {
        // prologue: issue row 0
        {
            const uint32_t stg = sbase + SM_STAGE;
            #pragma unroll
            for (int i = 0; i < 4; ++i) {
                const int p = tid + i * 256;
                const int samp = p >> 6, seg = p & 63;
                const int n = sIdx[samp];
                cp_async16(stg + samp * 1024 + seg * 16, feat + n * 256 + seg * 4);
            }
            CP_COMMIT();
        }
        for (int r = 0; r < 64; ++r) {
            if (r < 63) {
                const uint32_t stg = sbase + SM_STAGE + ((r + 1) & 1) * 16384;
                const int* ids = sIdx + (r + 1) * SAMP;
                #pragma unroll
                for (int i = 0; i < 4; ++i) {
                    const int p = tid + i * 256;
                    const int samp = p >> 6, seg = p & 63;
                    const int n = ids[samp];
                    cp_async16(stg + samp * 1024 + seg * 16, feat + n * 256 + seg * 4);
                }
                CP_COMMIT();
                CP_WAIT(1);
            } else {
                CP_WAIT(0);
            }
            __syncthreads();                    // chunk r visible to all
            if (tid < 64) {                     // 2 warps reduce: col = tid (float4)
                const char* stg = smem + SM_STAGE + (r & 1) * 16384;
                float4 a = make_float4(0.f, 0.f, 0.f, 0.f);
                #pragma unroll
                for (int s = 0; s < SAMP; ++s) {
                    float4 v = *(const float4*)(stg + s * 1024 + tid * 16);
                    a.x += v.x; a.y += v.y; a.z += v.z; a.w += v.w;
                }
                const float inv = 1.f / 16.f;
                a.x *= inv; a.y *= inv; a.z *= inv; a.w *= inv;
                __nv_bfloat162 h01 = __floats2bfloat162_rn(a.x, a.y);
                __nv_bfloat162 h23 = __floats2bfloat162_rn(a.z, a.w);
                float2 f01 = __bfloat1622float2(h01);
                float2 f23 = __bfloat1622float2(h23);
                __nv_bfloat162 l01 = __floats2bfloat162_rn(a.x - f01.x, a.y - f01.y);
                __nv_bfloat162 l23 = __floats2bfloat162_rn(a.z - f23.x, a.w - f23.y);
                *(uint2*)(smem + SM_AH + r * A_PITCH + tid * 8) =
                    make_uint2(*(uint32_t*)&h01, *(uint32_t*)&h23);
                *(uint2*)(smem + SM_AL + r * A_PITCH + tid * 8) =
                    make_uint2(*(uint32_t*)&l01, *(uint32_t*)&l23);
            }
            __syncthreads();                    // stage buffer reusable
        }
    }

    // ---------- Phase B: GEMM warp tile M64xN32, B fragments via LDG.64 (proven) ----------
    const int j0 = warp * 4;
    const uint32_t aAddrH = sbase + SM_AH + (uint32_t)(lane & 15) * A_PITCH + ((lane >> 4) << 4);
    const uint32_t aAddrL = aAddrH + (SM_AL - SM_AH);

    float c[4][4][4];
    #pragma unroll
    for (int mt = 0; mt < 4; ++mt)
        #pragma unroll
        for (int nt = 0; nt < 4; ++nt)
            #pragma unroll
            for (int r = 0; r < 4; ++r) c[mt][nt][r] = 0.f;

    uint2 bh[2][4], bl[2][4];
    {
        const uint32_t base = (uint32_t)(j0 * 32 + lane) * 2;
        #pragma unroll
        for (int nt = 0; nt < 4; ++nt) {
            bh[0][nt] = *(const uint2*)(g_Bfh + base + nt * 64);
            bl[0][nt] = *(const uint2*)(g_Bfl + base + nt * 64);
        }
    }

    #pragma unroll 2
    for (int i = 0; i < 16; ++i) {
        const int cur = i & 1, nxt = cur ^ 1;
        if (i < 15) {
            const uint32_t base = (uint32_t)((i + 1) * 1024 + j0 * 32 + lane) * 2;
            #pragma unroll
            for (int nt = 0; nt < 4; ++nt) {
                bh[nxt][nt] = *(const uint2*)(g_Bfh + base + nt * 64);
                bl[nxt][nt] = *(const uint2*)(g_Bfl + base + nt * 64);
            }
        }
        #pragma unroll
        for (int mt = 0; mt < 4; ++mt) {
            uint32_t aH[4], aL[4];
            const uint32_t ao = (uint32_t)(mt * 16) * A_PITCH + (uint32_t)(i * 32);
            ldsm4(aH[0], aH[1], aH[2], aH[3], aAddrH + ao);
            ldsm4(aL[0], aL[1], aL[2], aL[3], aAddrL + ao);
            #pragma unroll
            for (int nt = 0; nt < 4; ++nt) {
                mma_bf16(c[mt][nt], aH, (const uint32_t*)&bh[cur][nt]);
                mma_bf16(c[mt][nt], aH, (const uint32_t*)&bl[cur][nt]);
                mma_bf16(c[mt][nt], aL, (const uint32_t*)&bh[cur][nt]);
            }
        }
    }
    __syncthreads();                            // A/stage dead; rel overlays them

    // ---------- Phase C: relation means into smem (L1-resident table, proven) ----------
    {
        const float4* T4 = (const float4*)g_rwT;
        for (int i = 0; i < 8; ++i) {
            const int row = warp * 8 + i;
            const int* ids = rel + (b0 + row) * SAMP;
            float4 lo = make_float4(0.f, 0.f, 0.f, 0.f);
            float4 hi = make_float4(0.f, 0.f, 0.f, 0.f);
            #pragma unroll
            for (int s = 0; s < SAMP; ++s) {
                const int r = __ldg(ids + s);
                float4 vl = __ldg(&T4[r * 64 + lane]);
                float4 vh = __ldg(&T4[r * 64 + 32 + lane]);
                lo.x += vl.x; lo.y += vl.y; lo.z += vl.z; lo.w += vl.w;
                hi.x += vh.x; hi.y += vh.y; hi.z += vh.z; hi.w += vh.w;
            }
            const float inv = 1.f / 16.f;
            lo.x *= inv; lo.y *= inv; lo.z *= inv; lo.w *= inv;
            hi.x *= inv; hi.y *= inv; hi.z *= inv; hi.w *= inv;
            *(float4*)(smem + SM_REL + row * REL_PITCH_B + lane * 16)       = lo;
            *(float4*)(smem + SM_REL + row * REL_PITCH_B + 512 + lane * 16) = hi;
        }
    }
    __syncthreads();

    // ---------- Epilogue: + relation mean (smem), relu, streaming store ----------
    {
        const int colb = warp * 32 + (lane & 3) * 2;
        const int rowl = lane >> 2;
        #pragma unroll
        for (int mt = 0; mt < 4; ++mt) {
            const int r0l = rowl + mt * 16;
            const int r1l = r0l + 8;
            #pragma unroll
            for (int nt = 0; nt < 4; ++nt) {
                const int col = colb + nt * 8;
                float2 rv0 = *(const float2*)(smem + SM_REL + r0l * REL_PITCH_B + col * 4);
                float2 rv1 = *(const float2*)(smem + SM_REL + r1l * REL_PITCH_B + col * 4);
                float2 o0, o1;
                o0.x = fmaxf(c[mt][nt][0] + rv0.x, 0.f);
                o0.y = fmaxf(c[mt][nt][1] + rv0.y, 0.f);
                o1.x = fmaxf(c[mt][nt][2] + rv1.x, 0.f);
                o1.y = fmaxf(c[mt][nt][3] + rv1.y, 0.f);
                __stcs((float2*)&out[(b0 + r0l) * D + col], o0);
                __stcs((float2*)&out[(b0 + r1l) * D + col], o1);
            }
        }
    }
}

// ---------------- launch ----------------
extern "C" void kernel_launch(void* const* d_in, const int* in_sizes, int n_in,
                              void* d_out, int out_size) {
    (void)in_sizes; (void)n_in; (void)out_size;
    const int*   nbr  = (const int*)d_in[0];
    const int*   rel  = (const int*)d_in[1];
    const float* feat = (const float*)d_in[2];
    const float* W    = (const float*)d_in[3];
    const float* rw   = (const float*)d_in[4];
    float* out = (float*)d_out;

    cudaFuncSetAttribute(k_main, cudaFuncAttributeMaxDynamicSharedMemorySize, SM_TOTAL);

    k_prep0<<<NREL, 256>>>(rw, W);
    k_main<<<B_TOT / BM, NTHREADS, SM_TOTAL>>>(nbr, rel, feat, out);
}

// round 15
// speedup vs baseline: 1.3556x; 1.3556x over previous
#include <cuda_runtime.h>
#include <cuda_bf16.h>
#include <cstdint>

#define B_TOT   32768
#define SAMP    16
#define D       256
#define NREL    238
#define BM      64
#define NTHREADS 256

// ---------------- device-global scratch ----------------
// W packed as tf32 B-fragments for mma.m16n8k8.row.col:
// entry e = i*1024 + j*32 + lane  (i = k8-step 0..31, j = 8-col n-tile 0..31)
// holds {W[n][k], W[n][k+4]} with n = j*8 + (lane>>2), k = i*8 + (lane&3).
__device__ __align__(16) uint2 g_Bf[32768];       // 256 KB
__device__ __align__(16) float g_rwT[NREL * D];   // relation_weight transposed [r][d]

// ---------------- smem layout for k_main (bytes) ----------------
#define SM_IDX   0              // 1024 ints = 4096
#define SM_A     4096           // 64 rows * 1040 B (256 fp32 + 16B pad) = 66560
#define SM_REL   4096           // overlays A after GEMM: 64 * 1040
#define SM_TOTAL 70656
#define A_PITCH  1040           // 260 words; 260 % 32 = 4 -> conflict-free ldsm/STS
#define REL_PITCH_B 1040

// ---------------- helpers ----------------
__device__ __forceinline__ uint32_t smem_u32(const void* p) {
    uint32_t a;
    asm("{ .reg .u64 t; cvta.to.shared.u64 t, %1; cvt.u32.u64 %0, t; }" : "=r"(a) : "l"(p));
    return a;
}
// ldmatrix.x4.b16 on a 16-row x 32B fp32 tile == tf32 m16n8k8 A fragment:
// a0=(r,c) a1=(r+8,c) a2=(r,c+4) a3=(r+8,c+4), r=lane>>2, c=lane&3.
__device__ __forceinline__ void ldsm4(uint32_t& r0, uint32_t& r1, uint32_t& r2,
                                      uint32_t& r3, uint32_t addr) {
    asm volatile("ldmatrix.sync.aligned.m8n8.x4.shared.b16 {%0,%1,%2,%3}, [%4];"
                 : "=r"(r0), "=r"(r1), "=r"(r2), "=r"(r3) : "r"(addr));
}
__device__ __forceinline__ void mma_tf32(float* c, const uint32_t* a, const uint32_t* b) {
    asm volatile("mma.sync.aligned.m16n8k8.row.col.f32.tf32.tf32.f32 "
                 "{%0,%1,%2,%3}, {%4,%5,%6,%7}, {%8,%9}, {%0,%1,%2,%3};"
                 : "+f"(c[0]), "+f"(c[1]), "+f"(c[2]), "+f"(c[3])
                 : "r"(a[0]), "r"(a[1]), "r"(a[2]), "r"(a[3]), "r"(b[0]), "r"(b[1]));
}

// ---------------- kernel 0: transpose rw + pack W tf32 fragments ----------------
__global__ void k_prep0(const float* __restrict__ rw, const float* __restrict__ W) {
    const int tid = threadIdx.x;
    const int bx  = blockIdx.x;

    g_rwT[bx * D + tid] = rw[tid * NREL + bx];

    if (bx < 64) {
        #pragma unroll
        for (int r = 0; r < 2; ++r) {
            const int e = bx * 512 + r * 256 + tid;   // 0..32767
            const int l = e & 31;
            const int j = (e >> 5) & 31;
            const int i = e >> 10;
            const int n = j * 8 + (l >> 2);
            const int k = i * 8 + (l & 3);
            uint2 v;
            v.x = __float_as_uint(W[n * 256 + k]);
            v.y = __float_as_uint(W[n * 256 + k + 4]);
            g_Bf[e] = v;
        }
    }
}

// ---------------- kernel 1: gather+mean -> tf32 mma GEMM -> rel -> epilogue ----------
__global__ __launch_bounds__(NTHREADS, 2) void k_main(const int* __restrict__ nbr,
                                                      const int* __restrict__ rel,
                                                      const float* __restrict__ feat,
                                                      float* __restrict__ out) {
    extern __shared__ char smem[];
    const uint32_t sbase = smem_u32(smem);
    const int tid  = threadIdx.x;
    const int b0   = blockIdx.x * BM;
    const int lane = tid & 31;
    const int warp = tid >> 5;

    ((int4*)(smem + SM_IDX))[tid] = ((const int4*)(nbr + b0 * SAMP))[tid];
    __syncthreads();

    // ---------- Phase A: gather + mean (L2-only), fp32 straight to smem ----------
    {
        const int q = tid & 63;                 // float4 column
        const int g = tid >> 6;                 // 0..3 (warp-uniform row group)
        const float4* F4 = (const float4*)feat;
        const int* sIdx = (const int*)(smem + SM_IDX);
        #pragma unroll 2
        for (int k = 0; k < 16; ++k) {
            const int row = g * 16 + k;
            const int* ids = sIdx + row * SAMP;
            float4 a = make_float4(0.f, 0.f, 0.f, 0.f);
            #pragma unroll
            for (int s = 0; s < SAMP; ++s) {
                const int n = ids[s];
                float4 v = __ldcg(&F4[n * 64 + q]);
                a.x += v.x; a.y += v.y; a.z += v.z; a.w += v.w;
            }
            const float inv = 1.f / 16.f;
            a.x *= inv; a.y *= inv; a.z *= inv; a.w *= inv;
            *(float4*)(smem + SM_A + row * A_PITCH + q * 16) = a;
        }
    }
    __syncthreads();

    // ---------- Phase B: GEMM warp tile M64xN32, tf32 single pass ----------
    const int j0 = warp * 4;                    // 4 distinct 8-col n-tiles per warp
    const uint32_t aAddr = sbase + SM_A + (uint32_t)(lane & 15) * A_PITCH + ((lane >> 4) << 4);

    float c[4][4][4];                           // [mt][nt][frag]
    #pragma unroll
    for (int mt = 0; mt < 4; ++mt)
        #pragma unroll
        for (int nt = 0; nt < 4; ++nt)
            #pragma unroll
            for (int r = 0; r < 4; ++r) c[mt][nt][r] = 0.f;

    uint2 bf[2][4];                             // double-buffered B fragments
    {
        const int base = j0 * 32 + lane;
        #pragma unroll
        for (int nt = 0; nt < 4; ++nt) bf[0][nt] = g_Bf[base + nt * 32];
    }

    #pragma unroll 4
    for (int i = 0; i < 32; ++i) {              // 32 k8-steps
        const int cur = i & 1, nxt = cur ^ 1;
        if (i < 31) {
            const int base = (i + 1) * 1024 + j0 * 32 + lane;
            #pragma unroll
            for (int nt = 0; nt < 4; ++nt) bf[nxt][nt] = g_Bf[base + nt * 32];
        }
        #pragma unroll
        for (int mt = 0; mt < 4; ++mt) {
            uint32_t aF[4];
            ldsm4(aF[0], aF[1], aF[2], aF[3],
                  aAddr + (uint32_t)(mt * 16) * A_PITCH + (uint32_t)(i * 32));
            #pragma unroll
            for (int nt = 0; nt < 4; ++nt)
                mma_tf32(c[mt][nt], aF, (const uint32_t*)&bf[cur][nt]);
        }
    }
    __syncthreads();                            // A tiles dead; rel overlays them

    // ---------- Phase C: relation means into smem (L1-resident table, proven) ----------
    {
        const float4* T4 = (const float4*)g_rwT;
        for (int i = 0; i < 8; ++i) {
            const int row = warp * 8 + i;
            const int* ids = rel + (b0 + row) * SAMP;
            float4 lo = make_float4(0.f, 0.f, 0.f, 0.f);
            float4 hi = make_float4(0.f, 0.f, 0.f, 0.f);
            #pragma unroll
            for (int s = 0; s < SAMP; ++s) {
                const int r = __ldg(ids + s);
                float4 vl = __ldg(&T4[r * 64 + lane]);
                float4 vh = __ldg(&T4[r * 64 + 32 + lane]);
                lo.x += vl.x; lo.y += vl.y; lo.z += vl.z; lo.w += vl.w;
                hi.x += vh.x; hi.y += vh.y; hi.z += vh.z; hi.w += vh.w;
            }
            const float inv = 1.f / 16.f;
            lo.x *= inv; lo.y *= inv; lo.z *= inv; lo.w *= inv;
            hi.x *= inv; hi.y *= inv; hi.z *= inv; hi.w *= inv;
            *(float4*)(smem + SM_REL + row * REL_PITCH_B + lane * 16)       = lo;
            *(float4*)(smem + SM_REL + row * REL_PITCH_B + 512 + lane * 16) = hi;
        }
    }
    __syncthreads();

    // ---------- Epilogue: + relation mean (smem), relu, streaming store ----------
    {
        const int colb = warp * 32 + (lane & 3) * 2;
        const int rowl = lane >> 2;
        #pragma unroll
        for (int mt = 0; mt < 4; ++mt) {
            const int r0l = rowl + mt * 16;
            const int r1l = r0l + 8;
            #pragma unroll
            for (int nt = 0; nt < 4; ++nt) {
                const int col = colb + nt * 8;
                float2 rv0 = *(const float2*)(smem + SM_REL + r0l * REL_PITCH_B + col * 4);
                float2 rv1 = *(const float2*)(smem + SM_REL + r1l * REL_PITCH_B + col * 4);
                float2 o0, o1;
                o0.x = fmaxf(c[mt][nt][0] + rv0.x, 0.f);
                o0.y = fmaxf(c[mt][nt][1] + rv0.y, 0.f);
                o1.x = fmaxf(c[mt][nt][2] + rv1.x, 0.f);
                o1.y = fmaxf(c[mt][nt][3] + rv1.y, 0.f);
                __stcs((float2*)&out[(b0 + r0l) * D + col], o0);
                __stcs((float2*)&out[(b0 + r1l) * D + col], o1);
            }
        }
    }
}

// ---------------- launch ----------------
extern "C" void kernel_launch(void* const* d_in, const int* in_sizes, int n_in,
                              void* d_out, int out_size) {
    (void)in_sizes; (void)n_in; (void)out_size;
    const int*   nbr  = (const int*)d_in[0];
    const int*   rel  = (const int*)d_in[1];
    const float* feat = (const float*)d_in[2];
    const float* W    = (const float*)d_in[3];
    const float* rw   = (const float*)d_in[4];
    float* out = (float*)d_out;

    cudaFuncSetAttribute(k_main, cudaFuncAttributeMaxDynamicSharedMemorySize, SM_TOTAL);

    k_prep0<<<NREL, 256>>>(rw, W);
    k_main<<<B_TOT / BM, NTHREADS, SM_TOTAL>>>(nbr, rel, feat, out);
}